// round 15
// baseline (speedup 1.0000x reference)
#include <cuda_runtime.h>
#include <cuda.h>
#include <cuda_fp16.h>
#include <math.h>
#include <stdint.h>

// Problem constants
#define Tn   4096
#define Hn   2048
#define En   32
#define Kn   4
#define Fn   1408
#define F2n  2816
#define FSn  5632
#define FS2n 11264
#define RPAD (Tn*Kn + En*128)     // 20480 expanded rows, expert segs 128-aligned
#define MT_E (RPAD/128)           // 160 expert M-tiles
#define MT_S (Tn/128)             // 32 shared-path M-tiles

// ---------------- device scratch ----------------
__device__ __align__(1024) __half g_gupT[(size_t)En*F2n*Hn];   // fp16 weights, transposed
__device__ __align__(1024) __half g_dwnT[(size_t)En*Hn*Fn];
__device__ __align__(1024) __half g_sguT[(size_t)FS2n*Hn];
__device__ __align__(1024) __half g_sdnT[(size_t)Hn*FSn];
__device__ __align__(1024) __half g_hid[(size_t)Tn*Hn];        // fp16 activations
__device__ __align__(1024) __half g_disp[(size_t)RPAD*Hn];
__device__ __align__(1024) __half g_act[(size_t)RPAD*Fn];
__device__ __align__(1024) __half g_sact[(size_t)Tn*FSn];
__device__ int   g_row_token[RPAD];
__device__ float g_row_rw[RPAD];
__device__ float g_rw[Tn*Kn];
__device__ float g_gate[Tn];
__device__ int   g_cnt[En];
__device__ int   g_off[En+1];
__device__ int   g_pos[Tn*Kn];
__device__ int   g_eidx[Tn*Kn];
__device__ int   g_tile_expert[MT_E];

// ---------------- PTX helpers ----------------
__device__ __forceinline__ uint32_t s2u(const void* p) {
    uint32_t a;
    asm("{ .reg .u64 t; cvta.to.shared.u64 t, %1; cvt.u32.u64 %0, t; }" : "=r"(a) : "l"(p));
    return a;
}
__device__ __forceinline__ uint32_t ctarank() {
    uint32_t r; asm("mov.u32 %0, %%cluster_ctarank;" : "=r"(r)); return r;
}
#define MBARRIER_INIT(addr, cnt) \
    asm volatile("mbarrier.init.shared.b64 [%0], %1;" :: "r"((uint32_t)(addr)), "r"((uint32_t)(cnt)) : "memory")
#define MBARRIER_EXPECT_TX(addr, bytes) \
    asm volatile("mbarrier.arrive.expect_tx.shared.b64 _, [%0], %1;" :: "r"((uint32_t)(addr)), "r"((uint32_t)(bytes)) : "memory")
#define MBARRIER_ARRIVE(addr) \
    asm volatile("mbarrier.arrive.shared.b64 _, [%0];" :: "r"((uint32_t)(addr)) : "memory")
#define MBARRIER_ARRIVE_CLUSTER(local_mbar_addr, target_rank) \
    asm volatile("{\n\t.reg .b32 remAddr32;\n\t" \
        "mapa.shared::cluster.u32 remAddr32, %0, %1;\n\t" \
        "mbarrier.arrive.shared::cluster.b64 _, [remAddr32];\n\t}" \
        :: "r"((uint32_t)(local_mbar_addr)), "r"((uint32_t)(target_rank)) : "memory")
#define MBARRIER_WAIT_PARITY(mbar_smem_addr, phase_parity) do { \
    uint32_t _mbar = (uint32_t)(mbar_smem_addr); \
    uint32_t _parity = (uint32_t)(phase_parity); \
    uint32_t _done; \
    asm volatile("{\n\t.reg .pred p;\n\t" \
        "mbarrier.try_wait.parity.acquire.cta.shared::cta.b64 p, [%1], %2;\n\t" \
        "selp.b32 %0, 1, 0, p;\n\t}" \
        : "=r"(_done) : "r"(_mbar), "r"(_parity) : "memory"); \
    if (!_done) { \
        asm volatile("{\n\t.reg .pred P1;\n\t" \
            "WAIT_LOOP_%=:\n\t" \
            "mbarrier.try_wait.parity.acquire.cta.shared::cta.b64 P1, [%0], %1, 0x989680;\n\t" \
            "@P1 bra.uni WAIT_DONE_%=;\n\t" \
            "bra.uni WAIT_LOOP_%=;\n\t" \
            "WAIT_DONE_%=:\n\t}" \
            :: "r"(_mbar), "r"(_parity) : "memory"); \
    } \
} while(0)
#define FENCE_PROXY_ASYNC() asm volatile("fence.proxy.async.shared::cta;" ::: "memory")
#define CLUSTER_SYNC() do { \
    asm volatile("barrier.cluster.arrive.aligned;" ::: "memory"); \
    asm volatile("barrier.cluster.wait.aligned;" ::: "memory"); \
} while(0)

__device__ __forceinline__ void tma3(uint32_t dst, const CUtensorMap* m,
                                     int cx, int cy, int cz, uint32_t mbar) {
    asm volatile(
        "cp.async.bulk.tensor.3d.shared::cta.global.tile.mbarrier::complete_tx::bytes "
        "[%0], [%1, {%2, %3, %4}], [%5];"
        :: "r"(dst), "l"(m), "r"(cx), "r"(cy), "r"(cz), "r"(mbar) : "memory");
}
__device__ __forceinline__ void tma3_mc(uint32_t dst, const CUtensorMap* m,
                                        int cx, int cy, int cz, uint32_t mbar, uint16_t mask) {
    asm volatile(
        "cp.async.bulk.tensor.3d.shared::cluster.global.tile.mbarrier::complete_tx::bytes.multicast::cluster "
        "[%0], [%1, {%2, %3, %4}], [%5], %6;"
        :: "r"(dst), "l"(m), "r"(cx), "r"(cy), "r"(cz), "r"(mbar), "h"(mask) : "memory");
}
__device__ __forceinline__ void ldsm4(uint32_t* q, uint32_t addr) {
    asm volatile("ldmatrix.sync.aligned.m8n8.x4.shared.b16 {%0,%1,%2,%3}, [%4];"
        : "=r"(q[0]), "=r"(q[1]), "=r"(q[2]), "=r"(q[3]) : "r"(addr));
}
__device__ __forceinline__ void mma_f16(float* c, const uint32_t* a, uint32_t b0, uint32_t b1) {
    asm volatile("mma.sync.aligned.m16n8k16.row.col.f32.f16.f16.f32 "
        "{%0,%1,%2,%3}, {%4,%5,%6,%7}, {%8,%9}, {%0,%1,%2,%3};"
        : "+f"(c[0]), "+f"(c[1]), "+f"(c[2]), "+f"(c[3])
        : "r"(a[0]), "r"(a[1]), "r"(a[2]), "r"(a[3]), "r"(b0), "r"(b1));
}

// ---------------- routing ----------------
__global__ void k_init() {
    int i = blockIdx.x * blockDim.x + threadIdx.x;
    if (i < En)   g_cnt[i] = 0;
    if (i < RPAD) g_row_token[i] = -1;
}

__global__ void k_zero(float* __restrict__ out) {
    size_t i = (size_t)blockIdx.x * blockDim.x + threadIdx.x;
    ((float4*)out)[i] = make_float4(0.f, 0.f, 0.f, 0.f);
}

// router + fp16 conversion of hidden (fused)
__global__ void k_router(const float* __restrict__ hs, const float* __restrict__ rw,
                         const float* __restrict__ gw) {
    __shared__ float sh[Hn];
    __shared__ float slog[En];
    __shared__ float sred[128];
    int t = blockIdx.x;
    const float* hrow = hs + (size_t)t * Hn;
    for (int i = threadIdx.x; i < Hn; i += 128) {
        float v = hrow[i];
        sh[i] = v;
        g_hid[(size_t)t * Hn + i] = __float2half_rn(v);
    }
    __syncthreads();
    int warp = threadIdx.x >> 5, lane = threadIdx.x & 31;
    #pragma unroll
    for (int eo = 0; eo < 8; eo++) {
        int e = (warp << 3) + eo;
        const float* w = rw + (size_t)e * Hn;
        float acc = 0.f;
        for (int h = lane; h < Hn; h += 32) acc = fmaf(sh[h], w[h], acc);
        #pragma unroll
        for (int o = 16; o; o >>= 1) acc += __shfl_down_sync(0xffffffffu, acc, o);
        if (lane == 0) slog[e] = acc;
    }
    float g = 0.f;
    for (int h = threadIdx.x; h < Hn; h += 128) g = fmaf(sh[h], gw[h], g);
    sred[threadIdx.x] = g;
    __syncthreads();
    for (int s = 64; s; s >>= 1) {
        if (threadIdx.x < s) sred[threadIdx.x] += sred[threadIdx.x + s];
        __syncthreads();
    }
    if (threadIdx.x == 0) {
        g_gate[t] = 1.f / (1.f + expf(-sred[0]));
        float mx = slog[0];
        for (int e = 1; e < En; e++) mx = fmaxf(mx, slog[e]);
        float p[En]; float sum = 0.f;
        for (int e = 0; e < En; e++) { p[e] = expf(slog[e] - mx); sum += p[e]; }
        float inv = 1.f / sum;
        for (int k = 0; k < Kn; k++) {
            int best = 0; float bp = p[0];
            for (int e = 1; e < En; e++) if (p[e] > bp) { bp = p[e]; best = e; }
            int i4 = t * Kn + k;
            g_eidx[i4] = best;
            g_rw[i4]   = bp * inv;
            g_pos[i4]  = atomicAdd(&g_cnt[best], 1);
            p[best] = -1.f;
        }
    }
}

// parallelized scan + tile-expert map (single block)
__global__ void k_scan() {
    __shared__ int off[En + 1];
    __shared__ int cnt[En];
    if (threadIdx.x == 0) {
        int o = 0; off[0] = 0; g_off[0] = 0;
        for (int e = 0; e < En; e++) {
            cnt[e] = g_cnt[e];
            o += (cnt[e] + 127) & ~127;
            off[e + 1] = o; g_off[e + 1] = o;
        }
    }
    __syncthreads();
    for (int t = threadIdx.x; t < MT_E; t += blockDim.x) {
        int r = t * 128, e = -1;
        #pragma unroll
        for (int x = 0; x < En; x++)
            if (r >= off[x] && r < off[x] + cnt[x]) { e = x; break; }
        g_tile_expert[t] = e;
    }
}

__global__ void k_scatter() {
    int i = blockIdx.x * blockDim.x + threadIdx.x;
    if (i >= Tn * Kn) return;
    int e = g_eidx[i];
    int row = g_off[e] + g_pos[i];
    g_row_token[row] = i >> 2;
    g_row_rw[row]    = g_rw[i];
}

// ---------------- conversions ----------------
// transpose + fp16: W[e][Kd][Nd] fp32 -> WT[e][ndst][Kd] fp16.
// Tile 64(k) x 32(n). Loads: 128B-coalesced fp32. Stores: per-warp __half2 runs.
// ILV=1 interleaves gate/up columns: dst col = 2*j (gate) / 2*(j-HALF)+1 (up)
template<int ILV>
__global__ void k_thalf(const float* __restrict__ W, __half* __restrict__ o,
                        int Kd, int Nd, int HALF) {
    __shared__ float s[64][33];
    int e = blockIdx.z;
    const float* Wp = W + (size_t)e * Kd * Nd;
    int n0 = blockIdx.x * 32, k0 = blockIdx.y * 64;
    int tx = threadIdx.x, ty = threadIdx.y;   // (32, 8)
    #pragma unroll
    for (int j = 0; j < 8; j++)
        s[ty + 8*j][tx] = Wp[(size_t)(k0 + ty + 8*j) * Nd + n0 + tx];
    __syncthreads();
    size_t ob = (size_t)e * Nd * Kd;
    #pragma unroll
    for (int r = 0; r < 4; r++) {
        int nloc = ty + 8*r;
        int jsrc = n0 + nloc;
        int nd = ILV ? (jsrc < HALF ? 2*jsrc : 2*(jsrc - HALF) + 1) : jsrc;
        __half2 h2 = __floats2half2_rn(s[2*tx][nloc], s[2*tx + 1][nloc]);
        *(__half2*)(o + ob + (size_t)nd * Kd + k0 + 2*tx) = h2;
    }
}

// gather fp16 hidden rows -> dispatched rows (zeros on padding)
__global__ void k_gather_h() {
    int row = blockIdx.x;
    int tid = threadIdx.x;
    int tok = g_row_token[row];
    int4* d = (int4*)(g_disp + (size_t)row * Hn);
    if (tok >= 0) d[tid] = ((const int4*)(g_hid + (size_t)tok * Hn))[tid];
    else          d[tid] = make_int4(0,0,0,0);
}

// ---------------- merged fp16 GEMM, CTA tile 128x128, 2 CTA/SM, cluster-2 ----------
// Adjacent bids (even, odd) share the same mtile (all X are even) -> same A tile,
// same expert; rank 0 multicasts A to both CTAs, each CTA loads its own B.
// Full barrier expects 32KB/stage (16K A mc + 16K B). A-refill gated by rank0's
// free barrier (257 = 256 local + 1 remote from rank1's tid0 post-drain).
// GU=1: [expert gate_up+SwiGLU->g_act] + [shared gate_up+SwiGLU->g_sact]
// GU=0: down-proj, LONGEST-FIRST (shared tiles first), atomics into out.
#define STAGE_BYTES 32768
#define SMEM_CTRL   1024
#define NSTAGE      3
#define GEMM_SMEM   (SMEM_CTRL + NSTAGE*STAGE_BYTES)

template<int GU>
__global__ void __launch_bounds__(256, 2) __cluster_dims__(2, 1, 1) k_mma(
    const __grid_constant__ CUtensorMap mA0,
    const __grid_constant__ CUtensorMap mB0,
    const __grid_constant__ CUtensorMap mA1,
    const __grid_constant__ CUtensorMap mB1,
    float* __restrict__ out)
{
    extern __shared__ __align__(1024) char smem[];
    int bid = blockIdx.x;
    int path, xi, mtile;
    if (GU) {
        const int X0 = F2n/128;          // 22
        const int C0 = X0 * MT_E;        // even
        const int X1 = FS2n/128;         // 88
        if (bid < C0) { path = 0; xi = bid % X0; mtile = bid / X0; }
        else { bid -= C0; path = 1; xi = bid % X1; mtile = bid / X1; }
    } else {
        const int X = Hn/128;            // 16
        const int C1 = X * MT_S;         // 512 shared tiles first (longest-first)
        if (bid < C1) { path = 1; xi = bid % X; mtile = bid / X; }
        else { bid -= C1; path = 0; xi = bid % X; mtile = bid / X; }
    }
    const int Kdim  = path ? (GU ? Hn : FSn) : (GU ? Hn : Fn);
    const int eid   = path ? 0 : g_tile_expert[mtile];
    if (!path && eid < 0) return;        // pair-consistent (same mtile)
    const CUtensorMap* pA = path ? &mA1 : &mA0;
    const CUtensorMap* pB = path ? &mB1 : &mB0;

    const uint32_t rank = ctarank();
    const int m0 = mtile * 128;
    const int n0 = xi * 128;
    const int tid  = threadIdx.x;
    const int lane = tid & 31;
    const int wid  = tid >> 5;
    const int mw = (wid >> 2) * 64;
    const int nw = (wid & 3) * 32;
    const uint32_t sb = s2u(smem);
    if (tid == 0) {
        #pragma unroll
        for (int s = 0; s < NSTAGE; s++) {
            MBARRIER_INIT(sb + 8*s, 1);
            MBARRIER_INIT(sb + 64 + 8*s, rank == 0 ? 257 : 256);
        }
        FENCE_PROXY_ASYNC();
    }
    __syncthreads();
    CLUSTER_SYNC();   // barriers visible cluster-wide before multicast TMA

    const int nch = Kdim >> 6;
    const uint32_t st0 = sb + SMEM_CTRL;

    if (tid == 0) {
        #pragma unroll
        for (int c = 0; c < NSTAGE; c++) {
            uint32_t st = st0 + c * STAGE_BYTES;
            int kc = c << 6;
            MBARRIER_EXPECT_TX(sb + 8*c, STAGE_BYTES);
            if (rank == 0) tma3_mc(st, pA, kc, m0, 0, sb + 8*c, 3);
            tma3(st + 16384, pB, kc, n0, eid, sb + 8*c);
        }
    }

    float acc[4][4][4];
    #pragma unroll
    for (int i = 0; i < 4; i++)
        #pragma unroll
        for (int j = 0; j < 4; j++)
            #pragma unroll
            for (int q = 0; q < 4; q++) acc[i][j][q] = 0.f;

    const int r15 = lane & 15;
    const int cs  = lane >> 4;

    int s = 0, ph = 0;
    for (int c = 0; c < nch; c++) {
        MBARRIER_WAIT_PARITY(sb + 8*s, ph);
        const uint32_t st = st0 + s * STAGE_BYTES;
        #pragma unroll
        for (int kk = 0; kk < 4; kk++) {
            uint32_t aa[16], bb[8];
            #pragma unroll
            for (int mi = 0; mi < 4; mi++) {
                int row = mw + mi * 16 + r15;
                uint32_t off = row * 128 + ((((kk << 1) | cs) ^ (row & 7)) << 4);
                ldsm4(aa + 4*mi, st + off);
            }
            #pragma unroll
            for (int nj = 0; nj < 2; nj++) {
                int row = nw + nj * 16 + r15;
                uint32_t off = row * 128 + ((((kk << 1) | cs) ^ (row & 7)) << 4);
                ldsm4(bb + 4*nj, st + 16384 + off);
            }
            #pragma unroll
            for (int mi = 0; mi < 4; mi++) {
                #pragma unroll
                for (int ni = 0; ni < 4; ni++) {
                    int nj = ni >> 1, hf = ni & 1;
                    mma_f16(acc[mi][ni], aa + 4*mi, bb[4*nj + hf], bb[4*nj + 2 + hf]);
                }
            }
        }
        MBARRIER_ARRIVE(sb + 64 + 8*s);
        if (tid == 0 && c + NSTAGE < nch) {
            MBARRIER_WAIT_PARITY(sb + 64 + 8*s, ph);   // rank0: 257, rank1: 256
            if (rank == 1) MBARRIER_ARRIVE_CLUSTER(sb + 64 + 8*s, 0);  // unblock A refill
            int kc = (c + NSTAGE) << 6;
            MBARRIER_EXPECT_TX(sb + 8*s, STAGE_BYTES);
            if (rank == 0) tma3_mc(st, pA, kc, m0, 0, sb + 8*s, 3);
            tma3(st + 16384, pB, kc, n0, eid, sb + 8*s);
        }
        if (++s == NSTAGE) { s = 0; ph ^= 1; }
    }

    // epilogue
    const int er = lane >> 2;
    const int ec = (lane & 3) << 1;
    if (GU) {
        __half* Ch = path ? g_sact : g_act;
        const int NC = path ? FSn : Fn;
        #pragma unroll
        for (int mi = 0; mi < 4; mi++) {
            int r0 = m0 + mw + mi * 16 + er;
            #pragma unroll
            for (int ni = 0; ni < 4; ni++) {
                float v0 = acc[mi][ni][0], v1 = acc[mi][ni][1];
                float v2 = acc[mi][ni][2], v3 = acc[mi][ni][3];
                int j = (n0 + nw + ni * 8 + ec) >> 1;
                float a0 = v0 / (1.f + expf(-v0)) * v1;
                float a1 = v2 / (1.f + expf(-v2)) * v3;
                Ch[(size_t)r0 * NC + j]       = __float2half_rn(a0);
                Ch[(size_t)(r0 + 8) * NC + j] = __float2half_rn(a1);
            }
        }
    } else {
        #pragma unroll
        for (int mi = 0; mi < 4; mi++) {
            int r0 = m0 + mw + mi * 16 + er;
            int tok0, tok1; float w0, w1;
            if (path) {
                tok0 = r0; tok1 = r0 + 8;
                w0 = g_gate[tok0]; w1 = g_gate[tok1];
            } else {
                tok0 = g_row_token[r0];      w0 = g_row_rw[r0];
                tok1 = g_row_token[r0 + 8];  w1 = g_row_rw[r0 + 8];
            }
            #pragma unroll
            for (int ni = 0; ni < 4; ni++) {
                int col = n0 + nw + ni * 8 + ec;
                if (path || tok0 >= 0) {
                    atomicAdd(out + (size_t)tok0 * Hn + col,     w0 * acc[mi][ni][0]);
                    atomicAdd(out + (size_t)tok0 * Hn + col + 1, w0 * acc[mi][ni][1]);
                }
                if (path || tok1 >= 0) {
                    atomicAdd(out + (size_t)tok1 * Hn + col,     w1 * acc[mi][ni][2]);
                    atomicAdd(out + (size_t)tok1 * Hn + col + 1, w1 * acc[mi][ni][3]);
                }
            }
        }
    }
}

// ---------------- host launch ----------------
typedef CUresult (*encode_fn_t)(CUtensorMap*, CUtensorMapDataType, cuuint32_t, void*,
                                const cuuint64_t*, const cuuint64_t*, const cuuint32_t*,
                                const cuuint32_t*, CUtensorMapInterleave, CUtensorMapSwizzle,
                                CUtensorMapL2promotion, CUtensorMapFloatOOBfill);

static void mkmap(encode_fn_t enc, CUtensorMap* m, void* ptr,
                  uint64_t d0, uint64_t d1, uint64_t d2) {
    cuuint64_t dims[3] = {d0, d1, d2};
    cuuint64_t str[2]  = {d0 * 2, d0 * d1 * 2};
    cuuint32_t box[3]  = {64, 128, 1};
    cuuint32_t es[3]   = {1, 1, 1};
    enc(m, CU_TENSOR_MAP_DATA_TYPE_FLOAT16, 3, ptr, dims, str, box, es,
        CU_TENSOR_MAP_INTERLEAVE_NONE, CU_TENSOR_MAP_SWIZZLE_128B,
        CU_TENSOR_MAP_L2_PROMOTION_L2_128B, CU_TENSOR_MAP_FLOAT_OOB_FILL_NONE);
}

extern "C" void kernel_launch(void* const* d_in, const int* in_sizes, int n_in,
                              void* d_out, int out_size)
{
    const float* hs  = (const float*)d_in[0];
    const float* rw  = (const float*)d_in[1];
    const float* gup = (const float*)d_in[2];
    const float* dwn = (const float*)d_in[3];
    const float* sgu = (const float*)d_in[4];
    const float* sdn = (const float*)d_in[5];
    const float* sgw = (const float*)d_in[6];
    float* out = (float*)d_out;

    void* fp = nullptr;
    cudaDriverEntryPointQueryResult qr;
    cudaGetDriverEntryPointByVersion("cuTensorMapEncodeTiled", &fp, 12000,
                                     cudaEnableDefault, &qr);
    encode_fn_t enc = (encode_fn_t)fp;

    void *p_gupT, *p_dwnT, *p_sguT, *p_sdnT, *p_hid, *p_disp, *p_act, *p_sact;
    cudaGetSymbolAddress(&p_gupT, g_gupT);
    cudaGetSymbolAddress(&p_dwnT, g_dwnT);
    cudaGetSymbolAddress(&p_sguT, g_sguT);
    cudaGetSymbolAddress(&p_sdnT, g_sdnT);
    cudaGetSymbolAddress(&p_hid,  g_hid);
    cudaGetSymbolAddress(&p_disp, g_disp);
    cudaGetSymbolAddress(&p_act,  g_act);
    cudaGetSymbolAddress(&p_sact, g_sact);

    CUtensorMap mDisp, mGup, mAct, mDwn, mHid, mSgu, mSact, mSdn;
    mkmap(enc, &mDisp, p_disp, Hn,  RPAD, 1);
    mkmap(enc, &mGup,  p_gupT, Hn,  F2n,  En);
    mkmap(enc, &mAct,  p_act,  Fn,  RPAD, 1);
    mkmap(enc, &mDwn,  p_dwnT, Fn,  Hn,   En);
    mkmap(enc, &mHid,  p_hid,  Hn,  Tn,   1);
    mkmap(enc, &mSgu,  p_sguT, Hn,  FS2n, 1);
    mkmap(enc, &mSact, p_sact, FSn, Tn,   1);
    mkmap(enc, &mSdn,  p_sdnT, FSn, Hn,   1);

    cudaFuncSetAttribute(k_mma<0>, cudaFuncAttributeMaxDynamicSharedMemorySize, GEMM_SMEM);
    cudaFuncSetAttribute(k_mma<1>, cudaFuncAttributeMaxDynamicSharedMemorySize, GEMM_SMEM);

    // routing + dispatch + output zero-fill
    k_init<<<(RPAD + 255) / 256, 256>>>();
    k_zero<<<(Tn * Hn / 4) / 256, 256>>>(out);
    k_router<<<Tn, 128>>>(hs, rw, sgw);
    k_scan<<<1, 256>>>();
    k_scatter<<<64, 256>>>();

    // weight conversions (transpose + fp16; gate_up matrices interleaved)
    dim3 tb(32, 8);
    k_thalf<1><<<dim3(F2n/32,  Hn/64,  En), tb>>>(gup, (__half*)p_gupT, Hn,  F2n,  Fn);
    k_thalf<0><<<dim3(Hn/32,   Fn/64,  En), tb>>>(dwn, (__half*)p_dwnT, Fn,  Hn,   0);
    k_thalf<1><<<dim3(FS2n/32, Hn/64,  1 ), tb>>>(sgu, (__half*)p_sguT, Hn,  FS2n, FSn);
    k_thalf<0><<<dim3(Hn/32,   FSn/64, 1 ), tb>>>(sdn, (__half*)p_sdnT, FSn, Hn,   0);
    k_gather_h<<<RPAD, 256>>>();

    // merged gate_up+SwiGLU (expert + shared), cluster-2 A-multicast
    int gu_ctas = (F2n/128) * MT_E + (FS2n/128) * MT_S;    // 3520 + 2816 (even)
    k_mma<1><<<gu_ctas, 256, GEMM_SMEM>>>(mDisp, mGup, mHid, mSgu, nullptr);

    // merged down-proj, LONGEST-FIRST, cluster-2 A-multicast, atomics into out
    int dn_ctas = (Hn/128) * MT_E + (Hn/128) * MT_S;       // 2560 + 512 (even)
    k_mma<0><<<dn_ctas, 256, GEMM_SMEM>>>(mAct, mDwn, mSact, mSdn, out);
}

// round 16
// speedup vs baseline: 1.0126x; 1.0126x over previous
#include <cuda_runtime.h>
#include <cuda.h>
#include <cuda_fp16.h>
#include <math.h>
#include <stdint.h>

// Problem constants
#define Tn   4096
#define Hn   2048
#define En   32
#define Kn   4
#define Fn   1408
#define F2n  2816
#define FSn  5632
#define FS2n 11264
#define RPAD (Tn*Kn + En*128)     // 20480 expanded rows, expert segs 128-aligned
#define MT_E (RPAD/128)           // 160 expert M-tiles
#define MT_S (Tn/128)             // 32 shared-path M-tiles

// ---------------- device scratch ----------------
__device__ __align__(1024) __half g_gupT[(size_t)En*F2n*Hn];   // fp16 weights, transposed
__device__ __align__(1024) __half g_dwnT[(size_t)En*Hn*Fn];
__device__ __align__(1024) __half g_sguT[(size_t)FS2n*Hn];
__device__ __align__(1024) __half g_sdnT[(size_t)Hn*FSn];
__device__ __align__(1024) __half g_hid[(size_t)Tn*Hn];        // fp16 activations
__device__ __align__(1024) __half g_disp[(size_t)RPAD*Hn];
__device__ __align__(1024) __half g_act[(size_t)RPAD*Fn];
__device__ __align__(1024) __half g_sact[(size_t)Tn*FSn];
__device__ int   g_row_token[RPAD];
__device__ float g_row_rw[RPAD];
__device__ float g_rw[Tn*Kn];
__device__ float g_gate[Tn];
__device__ int   g_cnt[En];
__device__ int   g_off[En+1];
__device__ int   g_pos[Tn*Kn];
__device__ int   g_eidx[Tn*Kn];
__device__ int   g_tile_expert[MT_E];

// ---------------- PTX helpers ----------------
__device__ __forceinline__ uint32_t s2u(const void* p) {
    uint32_t a;
    asm("{ .reg .u64 t; cvta.to.shared.u64 t, %1; cvt.u32.u64 %0, t; }" : "=r"(a) : "l"(p));
    return a;
}
#define MBARRIER_INIT(addr, cnt) \
    asm volatile("mbarrier.init.shared.b64 [%0], %1;" :: "r"((uint32_t)(addr)), "r"((uint32_t)(cnt)) : "memory")
#define MBARRIER_EXPECT_TX(addr, bytes) \
    asm volatile("mbarrier.arrive.expect_tx.shared.b64 _, [%0], %1;" :: "r"((uint32_t)(addr)), "r"((uint32_t)(bytes)) : "memory")
#define MBARRIER_ARRIVE(addr) \
    asm volatile("mbarrier.arrive.shared.b64 _, [%0];" :: "r"((uint32_t)(addr)) : "memory")
#define MBARRIER_WAIT_PARITY(mbar_smem_addr, phase_parity) do { \
    uint32_t _mbar = (uint32_t)(mbar_smem_addr); \
    uint32_t _parity = (uint32_t)(phase_parity); \
    uint32_t _done; \
    asm volatile("{\n\t.reg .pred p;\n\t" \
        "mbarrier.try_wait.parity.acquire.cta.shared::cta.b64 p, [%1], %2;\n\t" \
        "selp.b32 %0, 1, 0, p;\n\t}" \
        : "=r"(_done) : "r"(_mbar), "r"(_parity) : "memory"); \
    if (!_done) { \
        asm volatile("{\n\t.reg .pred P1;\n\t" \
            "WAIT_LOOP_%=:\n\t" \
            "mbarrier.try_wait.parity.acquire.cta.shared::cta.b64 P1, [%0], %1, 0x989680;\n\t" \
            "@P1 bra.uni WAIT_DONE_%=;\n\t" \
            "bra.uni WAIT_LOOP_%=;\n\t" \
            "WAIT_DONE_%=:\n\t}" \
            :: "r"(_mbar), "r"(_parity) : "memory"); \
    } \
} while(0)
#define FENCE_PROXY_ASYNC() asm volatile("fence.proxy.async.shared::cta;" ::: "memory")

__device__ __forceinline__ void tma3(uint32_t dst, const CUtensorMap* m,
                                     int cx, int cy, int cz, uint32_t mbar) {
    asm volatile(
        "cp.async.bulk.tensor.3d.shared::cta.global.tile.mbarrier::complete_tx::bytes "
        "[%0], [%1, {%2, %3, %4}], [%5];"
        :: "r"(dst), "l"(m), "r"(cx), "r"(cy), "r"(cz), "r"(mbar) : "memory");
}
__device__ __forceinline__ void ldsm4(uint32_t* q, uint32_t addr) {
    asm volatile("ldmatrix.sync.aligned.m8n8.x4.shared.b16 {%0,%1,%2,%3}, [%4];"
        : "=r"(q[0]), "=r"(q[1]), "=r"(q[2]), "=r"(q[3]) : "r"(addr));
}
__device__ __forceinline__ void mma_f16(float* c, const uint32_t* a, uint32_t b0, uint32_t b1) {
    asm volatile("mma.sync.aligned.m16n8k16.row.col.f32.f16.f16.f32 "
        "{%0,%1,%2,%3}, {%4,%5,%6,%7}, {%8,%9}, {%0,%1,%2,%3};"
        : "+f"(c[0]), "+f"(c[1]), "+f"(c[2]), "+f"(c[3])
        : "r"(a[0]), "r"(a[1]), "r"(a[2]), "r"(a[3]), "r"(b0), "r"(b1));
}

// ---------------- routing ----------------
__global__ void k_init() {
    int i = blockIdx.x * blockDim.x + threadIdx.x;
    if (i < En)   g_cnt[i] = 0;
    if (i < RPAD) g_row_token[i] = -1;
}

__global__ void k_zero(float* __restrict__ out) {
    size_t i = (size_t)blockIdx.x * blockDim.x + threadIdx.x;
    ((float4*)out)[i] = make_float4(0.f, 0.f, 0.f, 0.f);
}

// router + fp16 conversion of hidden (fused)
__global__ void k_router(const float* __restrict__ hs, const float* __restrict__ rw,
                         const float* __restrict__ gw) {
    __shared__ float sh[Hn];
    __shared__ float slog[En];
    __shared__ float sred[128];
    int t = blockIdx.x;
    const float* hrow = hs + (size_t)t * Hn;
    for (int i = threadIdx.x; i < Hn; i += 128) {
        float v = hrow[i];
        sh[i] = v;
        g_hid[(size_t)t * Hn + i] = __float2half_rn(v);
    }
    __syncthreads();
    int warp = threadIdx.x >> 5, lane = threadIdx.x & 31;
    #pragma unroll
    for (int eo = 0; eo < 8; eo++) {
        int e = (warp << 3) + eo;
        const float* w = rw + (size_t)e * Hn;
        float acc = 0.f;
        for (int h = lane; h < Hn; h += 32) acc = fmaf(sh[h], w[h], acc);
        #pragma unroll
        for (int o = 16; o; o >>= 1) acc += __shfl_down_sync(0xffffffffu, acc, o);
        if (lane == 0) slog[e] = acc;
    }
    float g = 0.f;
    for (int h = threadIdx.x; h < Hn; h += 128) g = fmaf(sh[h], gw[h], g);
    sred[threadIdx.x] = g;
    __syncthreads();
    for (int s = 64; s; s >>= 1) {
        if (threadIdx.x < s) sred[threadIdx.x] += sred[threadIdx.x + s];
        __syncthreads();
    }
    if (threadIdx.x == 0) {
        g_gate[t] = 1.f / (1.f + expf(-sred[0]));
        float mx = slog[0];
        for (int e = 1; e < En; e++) mx = fmaxf(mx, slog[e]);
        float p[En]; float sum = 0.f;
        for (int e = 0; e < En; e++) { p[e] = expf(slog[e] - mx); sum += p[e]; }
        float inv = 1.f / sum;
        for (int k = 0; k < Kn; k++) {
            int best = 0; float bp = p[0];
            for (int e = 1; e < En; e++) if (p[e] > bp) { bp = p[e]; best = e; }
            int i4 = t * Kn + k;
            g_eidx[i4] = best;
            g_rw[i4]   = bp * inv;
            g_pos[i4]  = atomicAdd(&g_cnt[best], 1);
            p[best] = -1.f;
        }
    }
}

// parallelized scan + tile-expert map (single block)
__global__ void k_scan() {
    __shared__ int off[En + 1];
    __shared__ int cnt[En];
    if (threadIdx.x == 0) {
        int o = 0; off[0] = 0; g_off[0] = 0;
        for (int e = 0; e < En; e++) {
            cnt[e] = g_cnt[e];
            o += (cnt[e] + 127) & ~127;
            off[e + 1] = o; g_off[e + 1] = o;
        }
    }
    __syncthreads();
    for (int t = threadIdx.x; t < MT_E; t += blockDim.x) {
        int r = t * 128, e = -1;
        #pragma unroll
        for (int x = 0; x < En; x++)
            if (r >= off[x] && r < off[x] + cnt[x]) { e = x; break; }
        g_tile_expert[t] = e;
    }
}

__global__ void k_scatter() {
    int i = blockIdx.x * blockDim.x + threadIdx.x;
    if (i >= Tn * Kn) return;
    int e = g_eidx[i];
    int row = g_off[e] + g_pos[i];
    g_row_token[row] = i >> 2;
    g_row_rw[row]    = g_rw[i];
}

// ---------------- conversions ----------------
// transpose + fp16: W[e][Kd][Nd] fp32 -> WT[e][ndst][Kd] fp16.
// Tile 64(k) x 32(n). Loads: 128B-coalesced fp32. Stores: per-warp __half2 runs.
// ILV=1 interleaves gate/up columns: dst col = 2*j (gate) / 2*(j-HALF)+1 (up)
template<int ILV>
__global__ void k_thalf(const float* __restrict__ W, __half* __restrict__ o,
                        int Kd, int Nd, int HALF) {
    __shared__ float s[64][33];
    int e = blockIdx.z;
    const float* Wp = W + (size_t)e * Kd * Nd;
    int n0 = blockIdx.x * 32, k0 = blockIdx.y * 64;
    int tx = threadIdx.x, ty = threadIdx.y;   // (32, 8)
    #pragma unroll
    for (int j = 0; j < 8; j++)
        s[ty + 8*j][tx] = Wp[(size_t)(k0 + ty + 8*j) * Nd + n0 + tx];
    __syncthreads();
    size_t ob = (size_t)e * Nd * Kd;
    #pragma unroll
    for (int r = 0; r < 4; r++) {
        int nloc = ty + 8*r;
        int jsrc = n0 + nloc;
        int nd = ILV ? (jsrc < HALF ? 2*jsrc : 2*(jsrc - HALF) + 1) : jsrc;
        __half2 h2 = __floats2half2_rn(s[2*tx][nloc], s[2*tx + 1][nloc]);
        *(__half2*)(o + ob + (size_t)nd * Kd + k0 + 2*tx) = h2;
    }
}

// gather fp16 hidden rows -> dispatched rows (zeros on padding)
__global__ void k_gather_h() {
    int row = blockIdx.x;
    int tid = threadIdx.x;
    int tok = g_row_token[row];
    int4* d = (int4*)(g_disp + (size_t)row * Hn);
    if (tok >= 0) d[tid] = ((const int4*)(g_hid + (size_t)tok * Hn))[tid];
    else          d[tid] = make_int4(0,0,0,0);
}

// ---------------- merged fp16 GEMM, CTA tile 128x128, 4 warps, 2 CTA/SM ----------
// Warp tile 64x64 (2m x 2n): per kk 4 A-ldsm + 4 B-ldsm per warp = 32 ldsm/CTA
// (was 48 with 8 warps) -> 33% less LDS traffic, the R15-identified co-binder.
// GU=1: [expert gate_up+SwiGLU->g_act] + [shared gate_up+SwiGLU->g_sact]
// GU=0: down-proj, LONGEST-FIRST (shared tiles first), atomics into out.
#define STAGE_BYTES 32768
#define SMEM_CTRL   1024
#define NSTAGE      3
#define GEMM_SMEM   (SMEM_CTRL + NSTAGE*STAGE_BYTES)

template<int GU>
__global__ void __launch_bounds__(128, 2) k_mma(
    const __grid_constant__ CUtensorMap mA0,
    const __grid_constant__ CUtensorMap mB0,
    const __grid_constant__ CUtensorMap mA1,
    const __grid_constant__ CUtensorMap mB1,
    float* __restrict__ out)
{
    extern __shared__ __align__(1024) char smem[];
    int bid = blockIdx.x;
    int path, xi, mtile;
    if (GU) {
        const int X0 = F2n/128;          // 22
        const int C0 = X0 * MT_E;
        const int X1 = FS2n/128;         // 88
        if (bid < C0) { path = 0; xi = bid % X0; mtile = bid / X0; }
        else { bid -= C0; path = 1; xi = bid % X1; mtile = bid / X1; }
    } else {
        const int X = Hn/128;            // 16
        const int C1 = X * MT_S;         // 512 shared tiles first (longest-first)
        if (bid < C1) { path = 1; xi = bid % X; mtile = bid / X; }
        else { bid -= C1; path = 0; xi = bid % X; mtile = bid / X; }
    }
    const int Kdim  = path ? (GU ? Hn : FSn) : (GU ? Hn : Fn);
    const int eid   = path ? 0 : g_tile_expert[mtile];
    if (!path && eid < 0) return;
    const CUtensorMap* pA = path ? &mA1 : &mA0;
    const CUtensorMap* pB = path ? &mB1 : &mB0;

    const int m0 = mtile * 128;
    const int n0 = xi * 128;
    const int tid  = threadIdx.x;
    const int lane = tid & 31;
    const int wid  = tid >> 5;           // 0..3
    const int mw = (wid >> 1) * 64;      // 2 m-groups
    const int nw = (wid & 1) * 64;       // 2 n-groups
    const uint32_t sb = s2u(smem);
    if (tid == 0) {
        #pragma unroll
        for (int s = 0; s < NSTAGE; s++) {
            MBARRIER_INIT(sb + 8*s, 1);
            MBARRIER_INIT(sb + 64 + 8*s, 128);
        }
        FENCE_PROXY_ASYNC();
    }
    __syncthreads();

    const int nch = Kdim >> 6;
    const uint32_t st0 = sb + SMEM_CTRL;

    if (tid == 0) {
        #pragma unroll
        for (int c = 0; c < NSTAGE; c++) {
            uint32_t st = st0 + c * STAGE_BYTES;
            int kc = c << 6;
            MBARRIER_EXPECT_TX(sb + 8*c, STAGE_BYTES);
            tma3(st +     0, pA, kc, m0, 0,   sb + 8*c);
            tma3(st + 16384, pB, kc, n0, eid, sb + 8*c);
        }
    }

    float acc[4][8][4];
    #pragma unroll
    for (int i = 0; i < 4; i++)
        #pragma unroll
        for (int j = 0; j < 8; j++)
            #pragma unroll
            for (int q = 0; q < 4; q++) acc[i][j][q] = 0.f;

    const int r15 = lane & 15;
    const int cs  = lane >> 4;

    int s = 0, ph = 0;
    for (int c = 0; c < nch; c++) {
        MBARRIER_WAIT_PARITY(sb + 8*s, ph);
        const uint32_t st = st0 + s * STAGE_BYTES;
        #pragma unroll
        for (int kk = 0; kk < 4; kk++) {
            uint32_t aa[16], bb[16];
            #pragma unroll
            for (int mi = 0; mi < 4; mi++) {
                int row = mw + mi * 16 + r15;
                uint32_t off = row * 128 + ((((kk << 1) | cs) ^ (row & 7)) << 4);
                ldsm4(aa + 4*mi, st + off);
            }
            #pragma unroll
            for (int nj = 0; nj < 4; nj++) {
                int row = nw + nj * 16 + r15;
                uint32_t off = row * 128 + ((((kk << 1) | cs) ^ (row & 7)) << 4);
                ldsm4(bb + 4*nj, st + 16384 + off);
            }
            #pragma unroll
            for (int mi = 0; mi < 4; mi++) {
                #pragma unroll
                for (int ni = 0; ni < 8; ni++) {
                    int nj = ni >> 1, hf = ni & 1;
                    mma_f16(acc[mi][ni], aa + 4*mi, bb[4*nj + hf], bb[4*nj + 2 + hf]);
                }
            }
        }
        MBARRIER_ARRIVE(sb + 64 + 8*s);
        if (tid == 0 && c + NSTAGE < nch) {
            MBARRIER_WAIT_PARITY(sb + 64 + 8*s, ph);
            int kc = (c + NSTAGE) << 6;
            MBARRIER_EXPECT_TX(sb + 8*s, STAGE_BYTES);
            tma3(st +     0, pA, kc, m0, 0,   sb + 8*s);
            tma3(st + 16384, pB, kc, n0, eid, sb + 8*s);
        }
        if (++s == NSTAGE) { s = 0; ph ^= 1; }
    }

    // epilogue
    const int er = lane >> 2;
    const int ec = (lane & 3) << 1;
    if (GU) {
        __half* Ch = path ? g_sact : g_act;
        const int NC = path ? FSn : Fn;
        #pragma unroll
        for (int mi = 0; mi < 4; mi++) {
            int r0 = m0 + mw + mi * 16 + er;
            #pragma unroll
            for (int ni = 0; ni < 8; ni++) {
                float v0 = acc[mi][ni][0], v1 = acc[mi][ni][1];
                float v2 = acc[mi][ni][2], v3 = acc[mi][ni][3];
                int j = (n0 + nw + ni * 8 + ec) >> 1;
                float a0 = v0 / (1.f + expf(-v0)) * v1;
                float a1 = v2 / (1.f + expf(-v2)) * v3;
                Ch[(size_t)r0 * NC + j]       = __float2half_rn(a0);
                Ch[(size_t)(r0 + 8) * NC + j] = __float2half_rn(a1);
            }
        }
    } else {
        #pragma unroll
        for (int mi = 0; mi < 4; mi++) {
            int r0 = m0 + mw + mi * 16 + er;
            int tok0, tok1; float w0, w1;
            if (path) {
                tok0 = r0; tok1 = r0 + 8;
                w0 = g_gate[tok0]; w1 = g_gate[tok1];
            } else {
                tok0 = g_row_token[r0];      w0 = g_row_rw[r0];
                tok1 = g_row_token[r0 + 8];  w1 = g_row_rw[r0 + 8];
            }
            #pragma unroll
            for (int ni = 0; ni < 8; ni++) {
                int col = n0 + nw + ni * 8 + ec;
                if (path || tok0 >= 0) {
                    atomicAdd(out + (size_t)tok0 * Hn + col,     w0 * acc[mi][ni][0]);
                    atomicAdd(out + (size_t)tok0 * Hn + col + 1, w0 * acc[mi][ni][1]);
                }
                if (path || tok1 >= 0) {
                    atomicAdd(out + (size_t)tok1 * Hn + col,     w1 * acc[mi][ni][2]);
                    atomicAdd(out + (size_t)tok1 * Hn + col + 1, w1 * acc[mi][ni][3]);
                }
            }
        }
    }
}

// ---------------- host launch ----------------
typedef CUresult (*encode_fn_t)(CUtensorMap*, CUtensorMapDataType, cuuint32_t, void*,
                                const cuuint64_t*, const cuuint64_t*, const cuuint32_t*,
                                const cuuint32_t*, CUtensorMapInterleave, CUtensorMapSwizzle,
                                CUtensorMapL2promotion, CUtensorMapFloatOOBfill);

static void mkmap(encode_fn_t enc, CUtensorMap* m, void* ptr,
                  uint64_t d0, uint64_t d1, uint64_t d2) {
    cuuint64_t dims[3] = {d0, d1, d2};
    cuuint64_t str[2]  = {d0 * 2, d0 * d1 * 2};
    cuuint32_t box[3]  = {64, 128, 1};
    cuuint32_t es[3]   = {1, 1, 1};
    enc(m, CU_TENSOR_MAP_DATA_TYPE_FLOAT16, 3, ptr, dims, str, box, es,
        CU_TENSOR_MAP_INTERLEAVE_NONE, CU_TENSOR_MAP_SWIZZLE_128B,
        CU_TENSOR_MAP_L2_PROMOTION_L2_128B, CU_TENSOR_MAP_FLOAT_OOB_FILL_NONE);
}

extern "C" void kernel_launch(void* const* d_in, const int* in_sizes, int n_in,
                              void* d_out, int out_size)
{
    const float* hs  = (const float*)d_in[0];
    const float* rw  = (const float*)d_in[1];
    const float* gup = (const float*)d_in[2];
    const float* dwn = (const float*)d_in[3];
    const float* sgu = (const float*)d_in[4];
    const float* sdn = (const float*)d_in[5];
    const float* sgw = (const float*)d_in[6];
    float* out = (float*)d_out;

    void* fp = nullptr;
    cudaDriverEntryPointQueryResult qr;
    cudaGetDriverEntryPointByVersion("cuTensorMapEncodeTiled", &fp, 12000,
                                     cudaEnableDefault, &qr);
    encode_fn_t enc = (encode_fn_t)fp;

    void *p_gupT, *p_dwnT, *p_sguT, *p_sdnT, *p_hid, *p_disp, *p_act, *p_sact;
    cudaGetSymbolAddress(&p_gupT, g_gupT);
    cudaGetSymbolAddress(&p_dwnT, g_dwnT);
    cudaGetSymbolAddress(&p_sguT, g_sguT);
    cudaGetSymbolAddress(&p_sdnT, g_sdnT);
    cudaGetSymbolAddress(&p_hid,  g_hid);
    cudaGetSymbolAddress(&p_disp, g_disp);
    cudaGetSymbolAddress(&p_act,  g_act);
    cudaGetSymbolAddress(&p_sact, g_sact);

    CUtensorMap mDisp, mGup, mAct, mDwn, mHid, mSgu, mSact, mSdn;
    mkmap(enc, &mDisp, p_disp, Hn,  RPAD, 1);
    mkmap(enc, &mGup,  p_gupT, Hn,  F2n,  En);
    mkmap(enc, &mAct,  p_act,  Fn,  RPAD, 1);
    mkmap(enc, &mDwn,  p_dwnT, Fn,  Hn,   En);
    mkmap(enc, &mHid,  p_hid,  Hn,  Tn,   1);
    mkmap(enc, &mSgu,  p_sguT, Hn,  FS2n, 1);
    mkmap(enc, &mSact, p_sact, FSn, Tn,   1);
    mkmap(enc, &mSdn,  p_sdnT, FSn, Hn,   1);

    cudaFuncSetAttribute(k_mma<0>, cudaFuncAttributeMaxDynamicSharedMemorySize, GEMM_SMEM);
    cudaFuncSetAttribute(k_mma<1>, cudaFuncAttributeMaxDynamicSharedMemorySize, GEMM_SMEM);

    // routing + dispatch + output zero-fill
    k_init<<<(RPAD + 255) / 256, 256>>>();
    k_zero<<<(Tn * Hn / 4) / 256, 256>>>(out);
    k_router<<<Tn, 128>>>(hs, rw, sgw);
    k_scan<<<1, 256>>>();
    k_scatter<<<64, 256>>>();

    // weight conversions (transpose + fp16; gate_up matrices interleaved)
    dim3 tb(32, 8);
    k_thalf<1><<<dim3(F2n/32,  Hn/64,  En), tb>>>(gup, (__half*)p_gupT, Hn,  F2n,  Fn);
    k_thalf<0><<<dim3(Hn/32,   Fn/64,  En), tb>>>(dwn, (__half*)p_dwnT, Fn,  Hn,   0);
    k_thalf<1><<<dim3(FS2n/32, Hn/64,  1 ), tb>>>(sgu, (__half*)p_sguT, Hn,  FS2n, FSn);
    k_thalf<0><<<dim3(Hn/32,   FSn/64, 1 ), tb>>>(sdn, (__half*)p_sdnT, FSn, Hn,   0);
    k_gather_h<<<RPAD, 256>>>();

    // merged gate_up+SwiGLU (expert + shared)
    int gu_ctas = (F2n/128) * MT_E + (FS2n/128) * MT_S;    // 3520 + 2816
    k_mma<1><<<gu_ctas, 128, GEMM_SMEM>>>(mDisp, mGup, mHid, mSgu, nullptr);

    // merged down-proj, LONGEST-FIRST (shared tiles at bid 0), atomics into out
    int dn_ctas = (Hn/128) * MT_E + (Hn/128) * MT_S;       // 2560 + 512
    k_mma<0><<<dn_ctas, 128, GEMM_SMEM>>>(mAct, mDwn, mSact, mSdn, out);
}

// round 17
// speedup vs baseline: 1.0192x; 1.0065x over previous
#include <cuda_runtime.h>
#include <cuda.h>
#include <cuda_fp16.h>
#include <math.h>
#include <stdint.h>

// Problem constants
#define Tn   4096
#define Hn   2048
#define En   32
#define Kn   4
#define Fn   1408
#define F2n  2816
#define FSn  5632
#define FS2n 11264
#define RPAD (Tn*Kn + En*128)     // 20480 expanded rows, expert segs 128-aligned
#define MT_E (RPAD/128)           // 160 expert M-tiles
#define MT_S (Tn/128)             // 32 shared-path M-tiles

// ---------------- device scratch ----------------
__device__ __align__(1024) __half g_gupT[(size_t)En*F2n*Hn];   // fp16 weights, transposed
__device__ __align__(1024) __half g_dwnT[(size_t)En*Hn*Fn];
__device__ __align__(1024) __half g_sguT[(size_t)FS2n*Hn];
__device__ __align__(1024) __half g_sdnT[(size_t)Hn*FSn];
__device__ __align__(1024) __half g_hid[(size_t)Tn*Hn];        // fp16 activations
__device__ __align__(1024) __half g_disp[(size_t)RPAD*Hn];
__device__ __align__(1024) __half g_act[(size_t)RPAD*Fn];
__device__ __align__(1024) __half g_sact[(size_t)Tn*FSn];
__device__ int   g_row_token[RPAD];
__device__ float g_row_rw[RPAD];
__device__ float g_rw[Tn*Kn];
__device__ float g_gate[Tn];
__device__ int   g_cnt[En];
__device__ int   g_off[En+1];
__device__ int   g_pos[Tn*Kn];
__device__ int   g_eidx[Tn*Kn];
__device__ int   g_tile_expert[MT_E];

// ---------------- PTX helpers ----------------
__device__ __forceinline__ uint32_t s2u(const void* p) {
    uint32_t a;
    asm("{ .reg .u64 t; cvta.to.shared.u64 t, %1; cvt.u32.u64 %0, t; }" : "=r"(a) : "l"(p));
    return a;
}
#define MBARRIER_INIT(addr, cnt) \
    asm volatile("mbarrier.init.shared.b64 [%0], %1;" :: "r"((uint32_t)(addr)), "r"((uint32_t)(cnt)) : "memory")
#define MBARRIER_EXPECT_TX(addr, bytes) \
    asm volatile("mbarrier.arrive.expect_tx.shared.b64 _, [%0], %1;" :: "r"((uint32_t)(addr)), "r"((uint32_t)(bytes)) : "memory")
#define MBARRIER_ARRIVE(addr) \
    asm volatile("mbarrier.arrive.shared.b64 _, [%0];" :: "r"((uint32_t)(addr)) : "memory")
#define MBARRIER_WAIT_PARITY(mbar_smem_addr, phase_parity) do { \
    uint32_t _mbar = (uint32_t)(mbar_smem_addr); \
    uint32_t _parity = (uint32_t)(phase_parity); \
    uint32_t _done; \
    asm volatile("{\n\t.reg .pred p;\n\t" \
        "mbarrier.try_wait.parity.acquire.cta.shared::cta.b64 p, [%1], %2;\n\t" \
        "selp.b32 %0, 1, 0, p;\n\t}" \
        : "=r"(_done) : "r"(_mbar), "r"(_parity) : "memory"); \
    if (!_done) { \
        asm volatile("{\n\t.reg .pred P1;\n\t" \
            "WAIT_LOOP_%=:\n\t" \
            "mbarrier.try_wait.parity.acquire.cta.shared::cta.b64 P1, [%0], %1, 0x989680;\n\t" \
            "@P1 bra.uni WAIT_DONE_%=;\n\t" \
            "bra.uni WAIT_LOOP_%=;\n\t" \
            "WAIT_DONE_%=:\n\t}" \
            :: "r"(_mbar), "r"(_parity) : "memory"); \
    } \
} while(0)
#define FENCE_PROXY_ASYNC() asm volatile("fence.proxy.async.shared::cta;" ::: "memory")

__device__ __forceinline__ void tma3(uint32_t dst, const CUtensorMap* m,
                                     int cx, int cy, int cz, uint32_t mbar) {
    asm volatile(
        "cp.async.bulk.tensor.3d.shared::cta.global.tile.mbarrier::complete_tx::bytes "
        "[%0], [%1, {%2, %3, %4}], [%5];"
        :: "r"(dst), "l"(m), "r"(cx), "r"(cy), "r"(cz), "r"(mbar) : "memory");
}
__device__ __forceinline__ void ldsm4(uint32_t* q, uint32_t addr) {
    asm volatile("ldmatrix.sync.aligned.m8n8.x4.shared.b16 {%0,%1,%2,%3}, [%4];"
        : "=r"(q[0]), "=r"(q[1]), "=r"(q[2]), "=r"(q[3]) : "r"(addr));
}
__device__ __forceinline__ void mma_f16(float* c, const uint32_t* a, uint32_t b0, uint32_t b1) {
    asm volatile("mma.sync.aligned.m16n8k16.row.col.f32.f16.f16.f32 "
        "{%0,%1,%2,%3}, {%4,%5,%6,%7}, {%8,%9}, {%0,%1,%2,%3};"
        : "+f"(c[0]), "+f"(c[1]), "+f"(c[2]), "+f"(c[3])
        : "r"(a[0]), "r"(a[1]), "r"(a[2]), "r"(a[3]), "r"(b0), "r"(b1));
}

// ---------------- routing ----------------
// merged init + output zero-fill
__global__ void k_init(float* __restrict__ out) {
    int i = blockIdx.x * blockDim.x + threadIdx.x;
    if (i < En)   g_cnt[i] = 0;
    if (i < RPAD) g_row_token[i] = -1;
    if (i < Tn * Hn / 4)
        ((float4*)out)[i] = make_float4(0.f, 0.f, 0.f, 0.f);
}

// router + fp16 conversion of hidden (fused)
__global__ void k_router(const float* __restrict__ hs, const float* __restrict__ rw,
                         const float* __restrict__ gw) {
    __shared__ float sh[Hn];
    __shared__ float slog[En];
    __shared__ float sred[128];
    int t = blockIdx.x;
    const float* hrow = hs + (size_t)t * Hn;
    for (int i = threadIdx.x; i < Hn; i += 128) {
        float v = hrow[i];
        sh[i] = v;
        g_hid[(size_t)t * Hn + i] = __float2half_rn(v);
    }
    __syncthreads();
    int warp = threadIdx.x >> 5, lane = threadIdx.x & 31;
    #pragma unroll
    for (int eo = 0; eo < 8; eo++) {
        int e = (warp << 3) + eo;
        const float* w = rw + (size_t)e * Hn;
        float acc = 0.f;
        for (int h = lane; h < Hn; h += 32) acc = fmaf(sh[h], w[h], acc);
        #pragma unroll
        for (int o = 16; o; o >>= 1) acc += __shfl_down_sync(0xffffffffu, acc, o);
        if (lane == 0) slog[e] = acc;
    }
    float g = 0.f;
    for (int h = threadIdx.x; h < Hn; h += 128) g = fmaf(sh[h], gw[h], g);
    sred[threadIdx.x] = g;
    __syncthreads();
    for (int s = 64; s; s >>= 1) {
        if (threadIdx.x < s) sred[threadIdx.x] += sred[threadIdx.x + s];
        __syncthreads();
    }
    if (threadIdx.x == 0) {
        g_gate[t] = 1.f / (1.f + expf(-sred[0]));
        float mx = slog[0];
        for (int e = 1; e < En; e++) mx = fmaxf(mx, slog[e]);
        float p[En]; float sum = 0.f;
        for (int e = 0; e < En; e++) { p[e] = expf(slog[e] - mx); sum += p[e]; }
        float inv = 1.f / sum;
        for (int k = 0; k < Kn; k++) {
            int best = 0; float bp = p[0];
            for (int e = 1; e < En; e++) if (p[e] > bp) { bp = p[e]; best = e; }
            int i4 = t * Kn + k;
            g_eidx[i4] = best;
            g_rw[i4]   = bp * inv;
            g_pos[i4]  = atomicAdd(&g_cnt[best], 1);
            p[best] = -1.f;
        }
    }
}

// parallelized scan + tile-expert map (single block)
__global__ void k_scan() {
    __shared__ int off[En + 1];
    __shared__ int cnt[En];
    if (threadIdx.x == 0) {
        int o = 0; off[0] = 0; g_off[0] = 0;
        for (int e = 0; e < En; e++) {
            cnt[e] = g_cnt[e];
            o += (cnt[e] + 127) & ~127;
            off[e + 1] = o; g_off[e + 1] = o;
        }
    }
    __syncthreads();
    for (int t = threadIdx.x; t < MT_E; t += blockDim.x) {
        int r = t * 128, e = -1;
        #pragma unroll
        for (int x = 0; x < En; x++)
            if (r >= off[x] && r < off[x] + cnt[x]) { e = x; break; }
        g_tile_expert[t] = e;
    }
}

__global__ void k_scatter() {
    int i = blockIdx.x * blockDim.x + threadIdx.x;
    if (i >= Tn * Kn) return;
    int e = g_eidx[i];
    int row = g_off[e] + g_pos[i];
    g_row_token[row] = i >> 2;
    g_row_rw[row]    = g_rw[i];
}

// ---------------- conversions ----------------
// transpose + fp16: W[e][Kd][Nd] fp32 -> WT[e][ndst][Kd] fp16.
// Tile 64(k) x 32(n). Loads: 128B-coalesced fp32. Stores: per-warp __half2 runs.
// ILV=1 interleaves gate/up columns: dst col = 2*j (gate) / 2*(j-HALF)+1 (up)
template<int ILV>
__global__ void k_thalf(const float* __restrict__ W, __half* __restrict__ o,
                        int Kd, int Nd, int HALF) {
    __shared__ float s[64][33];
    int e = blockIdx.z;
    const float* Wp = W + (size_t)e * Kd * Nd;
    int n0 = blockIdx.x * 32, k0 = blockIdx.y * 64;
    int tx = threadIdx.x, ty = threadIdx.y;   // (32, 8)
    #pragma unroll
    for (int j = 0; j < 8; j++)
        s[ty + 8*j][tx] = Wp[(size_t)(k0 + ty + 8*j) * Nd + n0 + tx];
    __syncthreads();
    size_t ob = (size_t)e * Nd * Kd;
    #pragma unroll
    for (int r = 0; r < 4; r++) {
        int nloc = ty + 8*r;
        int jsrc = n0 + nloc;
        int nd = ILV ? (jsrc < HALF ? 2*jsrc : 2*(jsrc - HALF) + 1) : jsrc;
        __half2 h2 = __floats2half2_rn(s[2*tx][nloc], s[2*tx + 1][nloc]);
        *(__half2*)(o + ob + (size_t)nd * Kd + k0 + 2*tx) = h2;
    }
}

// gather fp16 hidden rows -> dispatched rows (zeros on padding)
__global__ void k_gather_h() {
    int row = blockIdx.x;
    int tid = threadIdx.x;
    int tok = g_row_token[row];
    int4* d = (int4*)(g_disp + (size_t)row * Hn);
    if (tok >= 0) d[tid] = ((const int4*)(g_hid + (size_t)tok * Hn))[tid];
    else          d[tid] = make_int4(0,0,0,0);
}

// ---------------- merged fp16 GEMM, CTA tile 128x128, 4 warps, 2 CTA/SM ----------
// Warp tile 64x64 (2m x 2n). GU epilogue: SwiGLU -> SMEM stage -> 128B-coalesced
// fp16 row-segment stores (fixes 4x sector write amplification).
// GU=1: [expert gate_up+SwiGLU->g_act] + [shared gate_up+SwiGLU->g_sact]
// GU=0: down-proj, LONGEST-FIRST (shared tiles first), atomics into out.
#define STAGE_BYTES 32768
#define SMEM_CTRL   1024
#define NSTAGE      3
#define GEMM_SMEM   (SMEM_CTRL + NSTAGE*STAGE_BYTES)

template<int GU>
__global__ void __launch_bounds__(128, 2) k_mma(
    const __grid_constant__ CUtensorMap mA0,
    const __grid_constant__ CUtensorMap mB0,
    const __grid_constant__ CUtensorMap mA1,
    const __grid_constant__ CUtensorMap mB1,
    float* __restrict__ out)
{
    extern __shared__ __align__(1024) char smem[];
    int bid = blockIdx.x;
    int path, xi, mtile;
    if (GU) {
        const int X0 = F2n/128;          // 22
        const int C0 = X0 * MT_E;
        const int X1 = FS2n/128;         // 88
        if (bid < C0) { path = 0; xi = bid % X0; mtile = bid / X0; }
        else { bid -= C0; path = 1; xi = bid % X1; mtile = bid / X1; }
    } else {
        const int X = Hn/128;            // 16
        const int C1 = X * MT_S;         // 512 shared tiles first (longest-first)
        if (bid < C1) { path = 1; xi = bid % X; mtile = bid / X; }
        else { bid -= C1; path = 0; xi = bid % X; mtile = bid / X; }
    }
    const int Kdim  = path ? (GU ? Hn : FSn) : (GU ? Hn : Fn);
    const int eid   = path ? 0 : g_tile_expert[mtile];
    if (!path && eid < 0) return;
    const CUtensorMap* pA = path ? &mA1 : &mA0;
    const CUtensorMap* pB = path ? &mB1 : &mB0;

    const int m0 = mtile * 128;
    const int n0 = xi * 128;
    const int tid  = threadIdx.x;
    const int lane = tid & 31;
    const int wid  = tid >> 5;           // 0..3
    const int mw = (wid >> 1) * 64;      // 2 m-groups
    const int nw = (wid & 1) * 64;       // 2 n-groups
    const uint32_t sb = s2u(smem);
    if (tid == 0) {
        #pragma unroll
        for (int s = 0; s < NSTAGE; s++) {
            MBARRIER_INIT(sb + 8*s, 1);
            MBARRIER_INIT(sb + 64 + 8*s, 128);
        }
        FENCE_PROXY_ASYNC();
    }
    __syncthreads();

    const int nch = Kdim >> 6;
    const uint32_t st0 = sb + SMEM_CTRL;

    if (tid == 0) {
        #pragma unroll
        for (int c = 0; c < NSTAGE; c++) {
            uint32_t st = st0 + c * STAGE_BYTES;
            int kc = c << 6;
            MBARRIER_EXPECT_TX(sb + 8*c, STAGE_BYTES);
            tma3(st +     0, pA, kc, m0, 0,   sb + 8*c);
            tma3(st + 16384, pB, kc, n0, eid, sb + 8*c);
        }
    }

    float acc[4][8][4];
    #pragma unroll
    for (int i = 0; i < 4; i++)
        #pragma unroll
        for (int j = 0; j < 8; j++)
            #pragma unroll
            for (int q = 0; q < 4; q++) acc[i][j][q] = 0.f;

    const int r15 = lane & 15;
    const int cs  = lane >> 4;

    int s = 0, ph = 0;
    for (int c = 0; c < nch; c++) {
        MBARRIER_WAIT_PARITY(sb + 8*s, ph);
        const uint32_t st = st0 + s * STAGE_BYTES;
        #pragma unroll
        for (int kk = 0; kk < 4; kk++) {
            uint32_t aa[16], bb[16];
            #pragma unroll
            for (int mi = 0; mi < 4; mi++) {
                int row = mw + mi * 16 + r15;
                uint32_t off = row * 128 + ((((kk << 1) | cs) ^ (row & 7)) << 4);
                ldsm4(aa + 4*mi, st + off);
            }
            #pragma unroll
            for (int nj = 0; nj < 4; nj++) {
                int row = nw + nj * 16 + r15;
                uint32_t off = row * 128 + ((((kk << 1) | cs) ^ (row & 7)) << 4);
                ldsm4(bb + 4*nj, st + 16384 + off);
            }
            #pragma unroll
            for (int mi = 0; mi < 4; mi++) {
                #pragma unroll
                for (int ni = 0; ni < 8; ni++) {
                    int nj = ni >> 1, hf = ni & 1;
                    mma_f16(acc[mi][ni], aa + 4*mi, bb[4*nj + hf], bb[4*nj + 2 + hf]);
                }
            }
        }
        MBARRIER_ARRIVE(sb + 64 + 8*s);
        if (tid == 0 && c + NSTAGE < nch) {
            MBARRIER_WAIT_PARITY(sb + 64 + 8*s, ph);
            int kc = (c + NSTAGE) << 6;
            MBARRIER_EXPECT_TX(sb + 8*s, STAGE_BYTES);
            tma3(st +     0, pA, kc, m0, 0,   sb + 8*s);
            tma3(st + 16384, pB, kc, n0, eid, sb + 8*s);
        }
        if (++s == NSTAGE) { s = 0; ph ^= 1; }
    }

    // epilogue
    const int er = lane >> 2;
    const int ec = (lane & 3) << 1;
    if (GU) {
        __half* Ch = path ? g_sact : g_act;
        const int NC = path ? FSn : Fn;
        // stage SwiGLU results in SMEM: tile = 128 rows x 64 halves (stride 66)
        __syncthreads();                     // all mainloop SMEM reads done
        __half* sst = (__half*)(smem + SMEM_CTRL);
        #pragma unroll
        for (int mi = 0; mi < 4; mi++) {
            int rl0 = mw + mi * 16 + er;     // local rows rl0, rl0+8
            #pragma unroll
            for (int ni = 0; ni < 8; ni++) {
                float v0 = acc[mi][ni][0], v1 = acc[mi][ni][1];
                float v2 = acc[mi][ni][2], v3 = acc[mi][ni][3];
                int jl = (nw + ni * 8 + ec) >> 1;   // local j column 0..63
                float a0 = v0 / (1.f + expf(-v0)) * v1;
                float a1 = v2 / (1.f + expf(-v2)) * v3;
                sst[rl0 * 66 + jl]       = __float2half_rn(a0);
                sst[(rl0 + 8) * 66 + jl] = __float2half_rn(a1);
            }
        }
        __syncthreads();
        // coalesced stores: 8 threads x 16B = 128B per row
        const int rrow = tid >> 3;           // 0..15
        const int seg  = (tid & 7) * 8;      // halves offset within row
        const size_t jbase = (size_t)(n0 >> 1);
        #pragma unroll
        for (int r8 = 0; r8 < 8; r8++) {
            int row = r8 * 16 + rrow;
            __half* src = sst + row * 66 + seg;
            uint4 v = make_uint4(*(uint32_t*)(src), *(uint32_t*)(src + 2),
                                 *(uint32_t*)(src + 4), *(uint32_t*)(src + 6));
            *(uint4*)(Ch + (size_t)(m0 + row) * NC + jbase + seg) = v;
        }
    } else {
        #pragma unroll
        for (int mi = 0; mi < 4; mi++) {
            int r0 = m0 + mw + mi * 16 + er;
            int tok0, tok1; float w0, w1;
            if (path) {
                tok0 = r0; tok1 = r0 + 8;
                w0 = g_gate[tok0]; w1 = g_gate[tok1];
            } else {
                tok0 = g_row_token[r0];      w0 = g_row_rw[r0];
                tok1 = g_row_token[r0 + 8];  w1 = g_row_rw[r0 + 8];
            }
            #pragma unroll
            for (int ni = 0; ni < 8; ni++) {
                int col = n0 + nw + ni * 8 + ec;
                if (path || tok0 >= 0) {
                    atomicAdd(out + (size_t)tok0 * Hn + col,     w0 * acc[mi][ni][0]);
                    atomicAdd(out + (size_t)tok0 * Hn + col + 1, w0 * acc[mi][ni][1]);
                }
                if (path || tok1 >= 0) {
                    atomicAdd(out + (size_t)tok1 * Hn + col,     w1 * acc[mi][ni][2]);
                    atomicAdd(out + (size_t)tok1 * Hn + col + 1, w1 * acc[mi][ni][3]);
                }
            }
        }
    }
}

// ---------------- host launch ----------------
typedef CUresult (*encode_fn_t)(CUtensorMap*, CUtensorMapDataType, cuuint32_t, void*,
                                const cuuint64_t*, const cuuint64_t*, const cuuint32_t*,
                                const cuuint32_t*, CUtensorMapInterleave, CUtensorMapSwizzle,
                                CUtensorMapL2promotion, CUtensorMapFloatOOBfill);

static void mkmap(encode_fn_t enc, CUtensorMap* m, void* ptr,
                  uint64_t d0, uint64_t d1, uint64_t d2) {
    cuuint64_t dims[3] = {d0, d1, d2};
    cuuint64_t str[2]  = {d0 * 2, d0 * d1 * 2};
    cuuint32_t box[3]  = {64, 128, 1};
    cuuint32_t es[3]   = {1, 1, 1};
    enc(m, CU_TENSOR_MAP_DATA_TYPE_FLOAT16, 3, ptr, dims, str, box, es,
        CU_TENSOR_MAP_INTERLEAVE_NONE, CU_TENSOR_MAP_SWIZZLE_128B,
        CU_TENSOR_MAP_L2_PROMOTION_L2_128B, CU_TENSOR_MAP_FLOAT_OOB_FILL_NONE);
}

extern "C" void kernel_launch(void* const* d_in, const int* in_sizes, int n_in,
                              void* d_out, int out_size)
{
    const float* hs  = (const float*)d_in[0];
    const float* rw  = (const float*)d_in[1];
    const float* gup = (const float*)d_in[2];
    const float* dwn = (const float*)d_in[3];
    const float* sgu = (const float*)d_in[4];
    const float* sdn = (const float*)d_in[5];
    const float* sgw = (const float*)d_in[6];
    float* out = (float*)d_out;

    void* fp = nullptr;
    cudaDriverEntryPointQueryResult qr;
    cudaGetDriverEntryPointByVersion("cuTensorMapEncodeTiled", &fp, 12000,
                                     cudaEnableDefault, &qr);
    encode_fn_t enc = (encode_fn_t)fp;

    void *p_gupT, *p_dwnT, *p_sguT, *p_sdnT, *p_hid, *p_disp, *p_act, *p_sact;
    cudaGetSymbolAddress(&p_gupT, g_gupT);
    cudaGetSymbolAddress(&p_dwnT, g_dwnT);
    cudaGetSymbolAddress(&p_sguT, g_sguT);
    cudaGetSymbolAddress(&p_sdnT, g_sdnT);
    cudaGetSymbolAddress(&p_hid,  g_hid);
    cudaGetSymbolAddress(&p_disp, g_disp);
    cudaGetSymbolAddress(&p_act,  g_act);
    cudaGetSymbolAddress(&p_sact, g_sact);

    CUtensorMap mDisp, mGup, mAct, mDwn, mHid, mSgu, mSact, mSdn;
    mkmap(enc, &mDisp, p_disp, Hn,  RPAD, 1);
    mkmap(enc, &mGup,  p_gupT, Hn,  F2n,  En);
    mkmap(enc, &mAct,  p_act,  Fn,  RPAD, 1);
    mkmap(enc, &mDwn,  p_dwnT, Fn,  Hn,   En);
    mkmap(enc, &mHid,  p_hid,  Hn,  Tn,   1);
    mkmap(enc, &mSgu,  p_sguT, Hn,  FS2n, 1);
    mkmap(enc, &mSact, p_sact, FSn, Tn,   1);
    mkmap(enc, &mSdn,  p_sdnT, FSn, Hn,   1);

    cudaFuncSetAttribute(k_mma<0>, cudaFuncAttributeMaxDynamicSharedMemorySize, GEMM_SMEM);
    cudaFuncSetAttribute(k_mma<1>, cudaFuncAttributeMaxDynamicSharedMemorySize, GEMM_SMEM);

    // routing + dispatch + output zero-fill (merged)
    k_init<<<(Tn * Hn / 4 + 255) / 256, 256>>>(out);
    k_router<<<Tn, 128>>>(hs, rw, sgw);
    k_scan<<<1, 256>>>();
    k_scatter<<<64, 256>>>();

    // weight conversions (transpose + fp16; gate_up matrices interleaved)
    dim3 tb(32, 8);
    k_thalf<1><<<dim3(F2n/32,  Hn/64,  En), tb>>>(gup, (__half*)p_gupT, Hn,  F2n,  Fn);
    k_thalf<0><<<dim3(Hn/32,   Fn/64,  En), tb>>>(dwn, (__half*)p_dwnT, Fn,  Hn,   0);
    k_thalf<1><<<dim3(FS2n/32, Hn/64,  1 ), tb>>>(sgu, (__half*)p_sguT, Hn,  FS2n, FSn);
    k_thalf<0><<<dim3(Hn/32,   FSn/64, 1 ), tb>>>(sdn, (__half*)p_sdnT, FSn, Hn,   0);
    k_gather_h<<<RPAD, 256>>>();

    // merged gate_up+SwiGLU (expert + shared)
    int gu_ctas = (F2n/128) * MT_E + (FS2n/128) * MT_S;    // 3520 + 2816
    k_mma<1><<<gu_ctas, 128, GEMM_SMEM>>>(mDisp, mGup, mHid, mSgu, nullptr);

    // merged down-proj, LONGEST-FIRST (shared tiles at bid 0), atomics into out
    int dn_ctas = (Hn/128) * MT_E + (Hn/128) * MT_S;       // 2560 + 512
    k_mma<0><<<dn_ctas, 128, GEMM_SMEM>>>(mAct, mDwn, mSact, mSdn, out);
}